// round 13
// baseline (speedup 1.0000x reference)
#include <cuda_runtime.h>
#include <math.h>

// Problem constants
#define NBATCH 8
#define NPTS   2048
#define NFEAT  32
#define NROWS  (NBATCH * NPTS)                       // 16384
#define NMAT   ((size_t)NBATCH * NPTS * NPTS)        // 33554432
#define MAX_IT 100

// eps = 0.1 ; log2-domain scale: (1/eps) * log2(e)
#define S2   14.4269504088896341f
#define LN2  0.6931471805599453f
#define EPSV 0.1f
#define LOG_MUV (logf(1.0f / 2048.0f + 1e-8f))      // == log_nu (N == M)
#define ERR_THRESH_SUM 0.8f

// Scratch (__device__ globals; no allocation allowed)
__device__ __align__(16) float g_u[NROWS];
__device__ __align__(16) float g_v[NROWS];
__device__ float g_err[MAX_IT];

__device__ __forceinline__ float ex2f(float x) {
    float y;
    asm("ex2.approx.ftz.f32 %0, %1;" : "=f"(y) : "f"(x));
    return y;
}
__device__ __forceinline__ float lg2f(float x) {
    float y;
    asm("lg2.approx.ftz.f32 %0, %1;" : "=f"(y) : "f"(x));
    return y;
}

// ---------------------------------------------------------------------------
// Init
// ---------------------------------------------------------------------------
__global__ void k_init(float* __restrict__ cost) {
    int t = blockIdx.x * blockDim.x + threadIdx.x;
    int n = gridDim.x * blockDim.x;
    for (int i = t; i < NROWS; i += n) {
        g_u[i] = 0.0f;
        g_v[i] = 0.0f;
    }
    if (t < MAX_IT) g_err[t] = 0.0f;
    if (t < NBATCH) cost[t] = 0.0f;
}

// ---------------------------------------------------------------------------
// Cost matrix: C[b,i,j] = sum_d (x[b,i,d] - y[b,j,d])^2
// ---------------------------------------------------------------------------
__global__ void __launch_bounds__(256) k_cost(const float* __restrict__ x,
                                              const float* __restrict__ y,
                                              float* __restrict__ C) {
    __shared__ float xs[NFEAT * 65];
    __shared__ float ys[NFEAT * 65];

    int tile = blockIdx.x;          // 8192 tiles of 64x64
    int b  = tile >> 10;
    int ti = (tile >> 5) & 31;
    int tj = tile & 31;
    int tid = threadIdx.x;

    const float* xb = x + ((size_t)b * NPTS + (size_t)ti * 64) * NFEAT;
    const float* yb = y + ((size_t)b * NPTS + (size_t)tj * 64) * NFEAT;

    for (int e = tid; e < 64 * NFEAT; e += 256) {
        int row = e >> 5;
        int d   = e & 31;
        xs[d * 65 + row] = xb[e];
        ys[d * 65 + row] = yb[e];
    }
    __syncthreads();

    int ri = (tid >> 4) << 2;
    int cj = (tid & 15) << 2;

    float acc[4][4];
#pragma unroll
    for (int a = 0; a < 4; a++)
#pragma unroll
        for (int c = 0; c < 4; c++) acc[a][c] = 0.0f;

#pragma unroll
    for (int d = 0; d < NFEAT; d++) {
        float xa[4], yv[4];
#pragma unroll
        for (int a = 0; a < 4; a++) xa[a] = xs[d * 65 + ri + a];
#pragma unroll
        for (int c = 0; c < 4; c++) yv[c] = ys[d * 65 + cj + c];
#pragma unroll
        for (int a = 0; a < 4; a++)
#pragma unroll
            for (int c = 0; c < 4; c++) {
                float diff = xa[a] - yv[c];
                acc[a][c] = fmaf(diff, diff, acc[a][c]);
            }
    }

    float* Cb = C + (size_t)b * NPTS * NPTS + (size_t)(ti * 64 + ri) * NPTS + (tj * 64 + cj);
#pragma unroll
    for (int a = 0; a < 4; a++) {
        float4 o = make_float4(acc[a][0], acc[a][1], acc[a][2], acc[a][3]);
        *reinterpret_cast<float4*>(Cb + (size_t)a * NPTS) = o;
    }
}

// ---------------------------------------------------------------------------
// Pipelined stage kernel: u-update for batch group gu AND v-update for batch
// group gv in ONE launch (different batches -> independent).
//   grid = 1280 blocks x 256 thr. bid%5==4 -> v-role (256 blocks), else
//   u-role (1024 blocks). Interleaving spreads both roles across all SMs, so
//   the u-role's DRAM streaming overlaps the v-role's L2-resident re-read of
//   the group streamed by the PREVIOUS stage.
// u-role  (R11 shape): warp per row, 8 rows/block, dual online-LSE chains.
// v-role: 32 cols/block, warp w covers rows [w*256,+256) in its column
//   strand (8 coalesced LDG.32 per step), dual chains, smem merge.
// itu/itv: iteration index per role; <0 disables the role.
// Early freeze (sticky): role skips if g_err[it-1] < thresh.
// ---------------------------------------------------------------------------
__global__ void __launch_bounds__(256, 7) k_stage(const float* __restrict__ C,
                                                  int gu, int gv,
                                                  int itu, int itv) {
    __shared__ float pot[NPTS];          // 8 KB : potential * S2
    __shared__ float pm_s[256];
    __shared__ float ps_s[256];
    __shared__ float blkerr;

    int bid = blockIdx.x;
    int tid = threadIdx.x;
    int w   = tid >> 5;
    int l   = tid & 31;
    int sub = bid % 5;

    if (sub == 4) {
        // ================= v-role =================
        if (itv < 0) return;
        if (itv > 0 && g_err[itv - 1] < ERR_THRESH_SUM) return;
        int v_idx = bid / 5;             // 0..255
        int b  = (gv << 2) + (v_idx >> 6);
        int jg = v_idx & 63;

        const float4* ug = reinterpret_cast<const float4*>(g_u + (b << 11));
        float4*       p4 = reinterpret_cast<float4*>(pot);
#pragma unroll
        for (int k = 0; k < 2; k++) {
            float4 t = ug[tid + (k << 8)];
            t.x *= S2; t.y *= S2; t.z *= S2; t.w *= S2;
            p4[tid + (k << 8)] = t;
        }
        __syncthreads();

        int j = (jg << 5) + l;
        const float* Cb = C + ((size_t)b << 22) + j;

        float m0 = -1e30f, s0 = 0.0f, m1 = -1e30f, s1 = 0.0f;
        int i0 = w << 8;                 // warp's 256-row segment
#pragma unroll 4
        for (int g = 0; g < 32; g++) {
            int i = i0 + (g << 3);
            const float* Ci = Cb + ((size_t)i << 11);
            float c0 = Ci[0];
            float c1 = Ci[(size_t)1 << 11];
            float c2 = Ci[(size_t)2 << 11];
            float c3 = Ci[(size_t)3 << 11];
            float c4 = Ci[(size_t)4 << 11];
            float c5 = Ci[(size_t)5 << 11];
            float c6 = Ci[(size_t)6 << 11];
            float c7 = Ci[(size_t)7 << 11];
            float t0 = fmaf(-S2, c0, pot[i + 0]);
            float t1 = fmaf(-S2, c1, pot[i + 1]);
            float t2 = fmaf(-S2, c2, pot[i + 2]);
            float t3 = fmaf(-S2, c3, pot[i + 3]);
            float t4 = fmaf(-S2, c4, pot[i + 4]);
            float t5 = fmaf(-S2, c5, pot[i + 5]);
            float t6 = fmaf(-S2, c6, pot[i + 6]);
            float t7 = fmaf(-S2, c7, pot[i + 7]);
            float mA = fmaxf(fmaxf(t0, t1), fmaxf(t2, t3));
            float n0 = fmaxf(m0, mA);
            s0 = s0 * ex2f(m0 - n0)
               + ((ex2f(t0 - n0) + ex2f(t1 - n0)) + (ex2f(t2 - n0) + ex2f(t3 - n0)));
            m0 = n0;
            float mB = fmaxf(fmaxf(t4, t5), fmaxf(t6, t7));
            float n1 = fmaxf(m1, mB);
            s1 = s1 * ex2f(m1 - n1)
               + ((ex2f(t4 - n1) + ex2f(t5 - n1)) + (ex2f(t6 - n1) + ex2f(t7 - n1)));
            m1 = n1;
        }
        float m = fmaxf(m0, m1);
        float s = s0 * ex2f(m0 - m) + s1 * ex2f(m1 - m);
        pm_s[(w << 5) + l] = m;
        ps_s[(w << 5) + l] = s;
        __syncthreads();

        if (w == 0) {
            float mm = pm_s[l], ss = ps_s[l];
#pragma unroll
            for (int k = 1; k < 8; k++) {
                float mo = pm_s[(k << 5) + l];
                float so = ps_s[(k << 5) + l];
                float nm = fmaxf(mm, mo);
                ss = ss * ex2f(mm - nm) + so * ex2f(mo - nm);
                mm = nm;
            }
            g_v[(b << 11) + j] = EPSV * (LOG_MUV - (mm + lg2f(ss)) * LN2);
        }
    } else {
        // ================= u-role =================
        if (itu < 0) return;
        if (itu > 0 && g_err[itu - 1] < ERR_THRESH_SUM) return;
        int u_idx = (bid / 5) * 4 + sub;         // 0..1023
        int b      = (gu << 2) + (u_idx >> 8);
        int rowblk = u_idx & 255;

        const float4* vg = reinterpret_cast<const float4*>(g_v + (b << 11));
        float4*       p4 = reinterpret_cast<float4*>(pot);
#pragma unroll
        for (int k = 0; k < 2; k++) {
            float4 t = vg[tid + (k << 8)];
            t.x *= S2; t.y *= S2; t.z *= S2; t.w *= S2;
            p4[tid + (k << 8)] = t;
        }
        if (tid == 0) blkerr = 0.0f;
        __syncthreads();

        int r = (b << 11) + (rowblk << 3) + w;
        const float4* Mr = reinterpret_cast<const float4*>(C + ((size_t)r << 11));

        float m0 = -1e30f, s0 = 0.0f, m1 = -1e30f, s1 = 0.0f;
#pragma unroll
        for (int g = 0; g < 8; g++) {
            int idx = l + (g << 6);
            float4 c0 = Mr[idx];
            float4 c1 = Mr[idx + 32];
            float4 v0 = p4[idx];
            float4 v1 = p4[idx + 32];
            float t0 = fmaf(-S2, c0.x, v0.x);
            float t1 = fmaf(-S2, c0.y, v0.y);
            float t2 = fmaf(-S2, c0.z, v0.z);
            float t3 = fmaf(-S2, c0.w, v0.w);
            float t4 = fmaf(-S2, c1.x, v1.x);
            float t5 = fmaf(-S2, c1.y, v1.y);
            float t6 = fmaf(-S2, c1.z, v1.z);
            float t7 = fmaf(-S2, c1.w, v1.w);
            float mA = fmaxf(fmaxf(t0, t1), fmaxf(t2, t3));
            float n0 = fmaxf(m0, mA);
            s0 = s0 * ex2f(m0 - n0)
               + ((ex2f(t0 - n0) + ex2f(t1 - n0)) + (ex2f(t2 - n0) + ex2f(t3 - n0)));
            m0 = n0;
            float mB = fmaxf(fmaxf(t4, t5), fmaxf(t6, t7));
            float n1 = fmaxf(m1, mB);
            s1 = s1 * ex2f(m1 - n1)
               + ((ex2f(t4 - n1) + ex2f(t5 - n1)) + (ex2f(t6 - n1) + ex2f(t7 - n1)));
            m1 = n1;
        }
        float m = fmaxf(m0, m1);
        float s = s0 * ex2f(m0 - m) + s1 * ex2f(m1 - m);
#pragma unroll
        for (int o = 16; o; o >>= 1) {
            float mo = __shfl_xor_sync(0xffffffffu, m, o);
            float so = __shfl_xor_sync(0xffffffffu, s, o);
            float nm = fmaxf(m, mo);
            s = s * ex2f(m - nm) + so * ex2f(mo - nm);
            m = nm;
        }
        if (l == 0) {
            float lse  = (m + lg2f(s)) * LN2;
            float pnew = EPSV * (LOG_MUV - lse);
            float du = fabsf(pnew - g_u[r]);
            g_u[r] = pnew;
            atomicAdd(&blkerr, du);
        }
        __syncthreads();
        if (tid == 0) atomicAdd(&g_err[itu], blkerr);
    }
}

// ---------------------------------------------------------------------------
// Epilogue: pi = exp((u_i + v_j - C_ij)/eps), cost[b] = sum pi*C
// ---------------------------------------------------------------------------
__global__ void __launch_bounds__(256) k_pi(const float* __restrict__ C,
                                            float* __restrict__ pi,
                                            float* __restrict__ cost) {
    __shared__ float blkcost;
    if (threadIdx.x == 0) blkcost = 0.0f;
    __syncthreads();

    int warp = (blockIdx.x << 3) + (threadIdx.x >> 5);
    int lane = threadIdx.x & 31;
    int r = warp;
    int b = r >> 11;

    float u = g_u[r];
    const float4* Cr = reinterpret_cast<const float4*>(C + (size_t)r * NPTS);
    const float4* Vr = reinterpret_cast<const float4*>(g_v + (b << 11));
    float4* Pr = reinterpret_cast<float4*>(pi + (size_t)r * NPTS);

    float acc = 0.0f;
#pragma unroll 4
    for (int k = lane; k < NPTS / 4; k += 32) {
        float4 c = Cr[k];
        float4 v = Vr[k];
        float4 p;
        p.x = ex2f((u + v.x - c.x) * S2);
        p.y = ex2f((u + v.y - c.y) * S2);
        p.z = ex2f((u + v.z - c.z) * S2);
        p.w = ex2f((u + v.w - c.w) * S2);
        Pr[k] = p;
        acc += p.x * c.x + p.y * c.y + p.z * c.z + p.w * c.w;
    }
#pragma unroll
    for (int o = 16; o; o >>= 1) acc += __shfl_xor_sync(0xffffffffu, acc, o);
    if (lane == 0) atomicAdd(&blkcost, acc);
    __syncthreads();
    if (threadIdx.x == 0) atomicAdd(&cost[b], blkcost);
}

// ---------------------------------------------------------------------------
// Launch: init -> cost -> 201-stage pipeline -> pi.
// Stage 2k   : u(A, k) + v(B, k-1)
// Stage 2k+1 : u(B, k) + v(A, k)
// Stage 200  : v(B, 99) only.
// Output layout (tuple order): cost[8] | pi | C.
// ---------------------------------------------------------------------------
extern "C" void kernel_launch(void* const* d_in, const int* in_sizes, int n_in,
                              void* d_out, int out_size) {
    const float* x = (const float*)d_in[0];
    const float* y = (const float*)d_in[1];
    float* out  = (float*)d_out;
    float* cost = out;
    float* pi   = out + NBATCH;
    float* C    = out + NBATCH + NMAT;

    const int G = 1280;   // 1024 u-role + 256 v-role blocks, interleaved

    k_init<<<64, 256>>>(cost);
    k_cost<<<NBATCH * 32 * 32, 256>>>(x, y, C);

    k_stage<<<G, 256>>>(C, 0, 0, 0, -1);             // s=0 : u(A,0)
    k_stage<<<G, 256>>>(C, 1, 0, 0, 0);              // s=1 : u(B,0) + v(A,0)
    for (int k = 1; k < MAX_IT; k++) {
        k_stage<<<G, 256>>>(C, 0, 1, k, k - 1);      // u(A,k) + v(B,k-1)
        k_stage<<<G, 256>>>(C, 1, 0, k, k);          // u(B,k) + v(A,k)
    }
    k_stage<<<G, 256>>>(C, 0, 1, -1, MAX_IT - 1);    // s=200 : v(B,99)

    k_pi<<<NROWS / 8, 256>>>(C, pi, cost);
}

// round 14
// speedup vs baseline: 1.2489x; 1.2489x over previous
#include <cuda_runtime.h>
#include <math.h>

// Problem constants
#define NBATCH 8
#define NPTS   2048
#define NFEAT  32
#define NROWS  (NBATCH * NPTS)                       // 16384
#define NMAT   ((size_t)NBATCH * NPTS * NPTS)        // 33554432
#define MAX_IT 100

// eps = 0.1 ; log2-domain scale: (1/eps) * log2(e)
#define S2   14.4269504088896341f
#define LN2  0.6931471805599453f
#define EPSV 0.1f
#define LOG_MUV (logf(1.0f / 2048.0f + 1e-8f))      // == log_nu (N == M)
#define ERR_THRESH_SUM 0.8f

// Scratch (__device__ globals; no allocation allowed)
__device__ __align__(16) float g_u[NROWS];
__device__ __align__(16) float g_v[NROWS];
__device__ float g_err[MAX_IT];

__device__ __forceinline__ float ex2f(float x) {
    float y;
    asm("ex2.approx.ftz.f32 %0, %1;" : "=f"(y) : "f"(x));
    return y;
}
__device__ __forceinline__ float lg2f(float x) {
    float y;
    asm("lg2.approx.ftz.f32 %0, %1;" : "=f"(y) : "f"(x));
    return y;
}

// ---------------------------------------------------------------------------
// Init
// ---------------------------------------------------------------------------
__global__ void k_init(float* __restrict__ cost) {
    int t = blockIdx.x * blockDim.x + threadIdx.x;
    int n = gridDim.x * blockDim.x;
    for (int i = t; i < NROWS; i += n) {
        g_u[i] = 0.0f;
        g_v[i] = 0.0f;
    }
    if (t < MAX_IT) g_err[t] = 0.0f;
    if (t < NBATCH) cost[t] = 0.0f;
}

// Dummy no-op: keeps the ncu capture slot aligned onto the first u half-sweep.
__global__ void k_dummy() {}

// ---------------------------------------------------------------------------
// Cost matrix: C[b,i,j] = sum_d (x[b,i,d] - y[b,j,d])^2
// ---------------------------------------------------------------------------
__global__ void __launch_bounds__(256) k_cost(const float* __restrict__ x,
                                              const float* __restrict__ y,
                                              float* __restrict__ C) {
    __shared__ float xs[NFEAT * 65];
    __shared__ float ys[NFEAT * 65];

    int tile = blockIdx.x;          // 8192 tiles of 64x64
    int b  = tile >> 10;
    int ti = (tile >> 5) & 31;
    int tj = tile & 31;
    int tid = threadIdx.x;

    const float* xb = x + ((size_t)b * NPTS + (size_t)ti * 64) * NFEAT;
    const float* yb = y + ((size_t)b * NPTS + (size_t)tj * 64) * NFEAT;

    for (int e = tid; e < 64 * NFEAT; e += 256) {
        int row = e >> 5;
        int d   = e & 31;
        xs[d * 65 + row] = xb[e];
        ys[d * 65 + row] = yb[e];
    }
    __syncthreads();

    int ri = (tid >> 4) << 2;
    int cj = (tid & 15) << 2;

    float acc[4][4];
#pragma unroll
    for (int a = 0; a < 4; a++)
#pragma unroll
        for (int c = 0; c < 4; c++) acc[a][c] = 0.0f;

#pragma unroll
    for (int d = 0; d < NFEAT; d++) {
        float xa[4], yv[4];
#pragma unroll
        for (int a = 0; a < 4; a++) xa[a] = xs[d * 65 + ri + a];
#pragma unroll
        for (int c = 0; c < 4; c++) yv[c] = ys[d * 65 + cj + c];
#pragma unroll
        for (int a = 0; a < 4; a++)
#pragma unroll
            for (int c = 0; c < 4; c++) {
                float diff = xa[a] - yv[c];
                acc[a][c] = fmaf(diff, diff, acc[a][c]);
            }
    }

    float* Cb = C + (size_t)b * NPTS * NPTS + (size_t)(ti * 64 + ri) * NPTS + (tj * 64 + cj);
#pragma unroll
    for (int a = 0; a < 4; a++) {
        float4 o = make_float4(acc[a][0], acc[a][1], acc[a][2], acc[a][3]);
        *reinterpret_cast<float4*>(Cb + (size_t)a * NPTS) = o;
    }
}

// ---------------------------------------------------------------------------
// u half-sweep (row LSE over C, batches [b0, b0+4), ascending).
// R11 shape: 256 thr, warp per row, dual online-LSE chains, 32 regs, 87% occ.
// ---------------------------------------------------------------------------
__global__ void __launch_bounds__(256, 7) k_sweep(const float* __restrict__ M,
                                                  int b0, int it) {
    if (it > 0 && g_err[it - 1] < ERR_THRESH_SUM) return;

    __shared__ float oS2[NPTS];          // 8 KB : v * S2
    __shared__ float blkerr;

    int blk = blockIdx.x;                // 1024 blocks, 8 rows each
    int b   = b0 + (blk >> 8);
    int tid = threadIdx.x;
    int w   = tid >> 5;
    int l   = tid & 31;

    const float4* og  = reinterpret_cast<const float4*>(g_v + (b << 11));
    float4*       os4 = reinterpret_cast<float4*>(oS2);
#pragma unroll
    for (int k = 0; k < 2; k++) {
        float4 t = og[tid + (k << 8)];
        t.x *= S2; t.y *= S2; t.z *= S2; t.w *= S2;
        os4[tid + (k << 8)] = t;
    }
    if (tid == 0) blkerr = 0.0f;
    __syncthreads();

    int r = (b << 11) + ((blk & 255) << 3) + w;      // global row index
    const float4* Mr = reinterpret_cast<const float4*>(M + ((size_t)r << 11));

    float m0 = -1e30f, s0 = 0.0f, m1 = -1e30f, s1 = 0.0f;
#pragma unroll
    for (int g = 0; g < 8; g++) {
        int idx = l + (g << 6);
        float4 c0 = Mr[idx];
        float4 c1 = Mr[idx + 32];
        float4 v0 = os4[idx];
        float4 v1 = os4[idx + 32];
        float t0 = fmaf(-S2, c0.x, v0.x);
        float t1 = fmaf(-S2, c0.y, v0.y);
        float t2 = fmaf(-S2, c0.z, v0.z);
        float t3 = fmaf(-S2, c0.w, v0.w);
        float t4 = fmaf(-S2, c1.x, v1.x);
        float t5 = fmaf(-S2, c1.y, v1.y);
        float t6 = fmaf(-S2, c1.z, v1.z);
        float t7 = fmaf(-S2, c1.w, v1.w);
        float mA = fmaxf(fmaxf(t0, t1), fmaxf(t2, t3));
        float n0 = fmaxf(m0, mA);
        s0 = s0 * ex2f(m0 - n0)
           + ((ex2f(t0 - n0) + ex2f(t1 - n0)) + (ex2f(t2 - n0) + ex2f(t3 - n0)));
        m0 = n0;
        float mB = fmaxf(fmaxf(t4, t5), fmaxf(t6, t7));
        float n1 = fmaxf(m1, mB);
        s1 = s1 * ex2f(m1 - n1)
           + ((ex2f(t4 - n1) + ex2f(t5 - n1)) + (ex2f(t6 - n1) + ex2f(t7 - n1)));
        m1 = n1;
    }
    float m = fmaxf(m0, m1);
    float s = s0 * ex2f(m0 - m) + s1 * ex2f(m1 - m);
#pragma unroll
    for (int o = 16; o; o >>= 1) {
        float mo = __shfl_xor_sync(0xffffffffu, m, o);
        float so = __shfl_xor_sync(0xffffffffu, s, o);
        float nm = fmaxf(m, mo);
        s = s * ex2f(m - nm) + so * ex2f(mo - nm);
        m = nm;
    }
    if (l == 0) {
        float lse  = (m + lg2f(s)) * LN2;
        float pnew = EPSV * (LOG_MUV - lse);
        float du = fabsf(pnew - g_u[r]);
        g_u[r] = pnew;
        atomicAdd(&blkerr, du);
    }
    __syncthreads();
    if (tid == 0) atomicAdd(&g_err[it], blkerr);
}

// ---------------------------------------------------------------------------
// v half-sweep: column LSE over C for batches [b0, b0+4), DESCENDING within
// the group (starts where the preceding u half-sweep just finished -> L2 hot).
// Block = 512 threads (16 warps), 32 columns; warp w owns rows [w*128, +128).
// ---------------------------------------------------------------------------
__global__ void __launch_bounds__(512) k_vcol(const float* __restrict__ C,
                                              int b0, int it) {
    if (it > 0 && g_err[it - 1] < ERR_THRESH_SUM) return;

    __shared__ float uS2_s[NPTS];        // 8 KB : u * S2
    __shared__ float pm_s[16 * 32];
    __shared__ float ps_s[16 * 32];

    int blk = blockIdx.x;                // 256 blocks
    int b   = b0 + 3 - (blk >> 6);       // descending within the group
    int jg  = blk & 63;                  // column group (32 cols)
    int tid = threadIdx.x;
    int w   = tid >> 5;
    int l   = tid & 31;

    const float4* ug  = reinterpret_cast<const float4*>(g_u + (b << 11));
    float4*       us4 = reinterpret_cast<float4*>(uS2_s);
    {
        float4 t = ug[tid];
        t.x *= S2; t.y *= S2; t.z *= S2; t.w *= S2;
        us4[tid] = t;
    }
    __syncthreads();

    int j = (jg << 5) + l;               // this thread's column
    const float* Cb = C + ((size_t)b << 22) + j;

    float m0 = -1e30f, s0 = 0.0f, m1 = -1e30f, s1 = 0.0f;
    int i0 = w << 7;                     // warp's 128-row segment
#pragma unroll 2
    for (int g = 0; g < 16; g++) {
        int i = i0 + (g << 3);
        const float* Ci = Cb + ((size_t)i << 11);
        float c0 = Ci[0];
        float c1 = Ci[(size_t)1 << 11];
        float c2 = Ci[(size_t)2 << 11];
        float c3 = Ci[(size_t)3 << 11];
        float c4 = Ci[(size_t)4 << 11];
        float c5 = Ci[(size_t)5 << 11];
        float c6 = Ci[(size_t)6 << 11];
        float c7 = Ci[(size_t)7 << 11];
        float t0 = fmaf(-S2, c0, uS2_s[i + 0]);
        float t1 = fmaf(-S2, c1, uS2_s[i + 1]);
        float t2 = fmaf(-S2, c2, uS2_s[i + 2]);
        float t3 = fmaf(-S2, c3, uS2_s[i + 3]);
        float t4 = fmaf(-S2, c4, uS2_s[i + 4]);
        float t5 = fmaf(-S2, c5, uS2_s[i + 5]);
        float t6 = fmaf(-S2, c6, uS2_s[i + 6]);
        float t7 = fmaf(-S2, c7, uS2_s[i + 7]);
        float mA = fmaxf(fmaxf(t0, t1), fmaxf(t2, t3));
        float n0 = fmaxf(m0, mA);
        s0 = s0 * ex2f(m0 - n0)
           + ((ex2f(t0 - n0) + ex2f(t1 - n0)) + (ex2f(t2 - n0) + ex2f(t3 - n0)));
        m0 = n0;
        float mB = fmaxf(fmaxf(t4, t5), fmaxf(t6, t7));
        float n1 = fmaxf(m1, mB);
        s1 = s1 * ex2f(m1 - n1)
           + ((ex2f(t4 - n1) + ex2f(t5 - n1)) + (ex2f(t6 - n1) + ex2f(t7 - n1)));
        m1 = n1;
    }
    float m = fmaxf(m0, m1);
    float s = s0 * ex2f(m0 - m) + s1 * ex2f(m1 - m);
    pm_s[(w << 5) + l] = m;
    ps_s[(w << 5) + l] = s;
    __syncthreads();

    if (w == 0) {
        float mm = pm_s[l], ss = ps_s[l];
#pragma unroll
        for (int k = 1; k < 16; k++) {
            float mo = pm_s[(k << 5) + l];
            float so = ps_s[(k << 5) + l];
            float nm = fmaxf(mm, mo);
            ss = ss * ex2f(mm - nm) + so * ex2f(mo - nm);
            mm = nm;
        }
        g_v[(b << 11) + j] = EPSV * (LOG_MUV - (mm + lg2f(ss)) * LN2);
    }
}

// ---------------------------------------------------------------------------
// Epilogue: pi = exp((u_i + v_j - C_ij)/eps), cost[b] = sum pi*C
// ---------------------------------------------------------------------------
__global__ void __launch_bounds__(256) k_pi(const float* __restrict__ C,
                                            float* __restrict__ pi,
                                            float* __restrict__ cost) {
    __shared__ float blkcost;
    if (threadIdx.x == 0) blkcost = 0.0f;
    __syncthreads();

    int warp = (blockIdx.x << 3) + (threadIdx.x >> 5);
    int lane = threadIdx.x & 31;
    int r = warp;
    int b = r >> 11;

    float u = g_u[r];
    const float4* Cr = reinterpret_cast<const float4*>(C + (size_t)r * NPTS);
    const float4* Vr = reinterpret_cast<const float4*>(g_v + (b << 11));
    float4* Pr = reinterpret_cast<float4*>(pi + (size_t)r * NPTS);

    float acc = 0.0f;
#pragma unroll 4
    for (int k = lane; k < NPTS / 4; k += 32) {
        float4 c = Cr[k];
        float4 v = Vr[k];
        float4 p;
        p.x = ex2f((u + v.x - c.x) * S2);
        p.y = ex2f((u + v.y - c.y) * S2);
        p.z = ex2f((u + v.z - c.z) * S2);
        p.w = ex2f((u + v.w - c.w) * S2);
        Pr[k] = p;
        acc += p.x * c.x + p.y * c.y + p.z * c.z + p.w * c.w;
    }
#pragma unroll
    for (int o = 16; o; o >>= 1) acc += __shfl_xor_sync(0xffffffffu, acc, o);
    if (lane == 0) atomicAdd(&blkcost, acc);
    __syncthreads();
    if (threadIdx.x == 0) atomicAdd(&cost[b], blkcost);
}

// ---------------------------------------------------------------------------
// Launch: init -> cost -> dummy -> 100 x (u(A); v(A); u(B); v(B)) -> pi.
// Group A = batches 0-3, B = 4-7. Each v(X) re-reads the 64 MB its u(X) just
// streamed (nothing in between -> L2-hot); boustrophedon order across halves.
// Output layout (tuple order): cost[8] | pi | C.
// ---------------------------------------------------------------------------
extern "C" void kernel_launch(void* const* d_in, const int* in_sizes, int n_in,
                              void* d_out, int out_size) {
    const float* x = (const float*)d_in[0];
    const float* y = (const float*)d_in[1];
    float* out  = (float*)d_out;
    float* cost = out;
    float* pi   = out + NBATCH;
    float* C    = out + NBATCH + NMAT;

    k_init<<<64, 256>>>(cost);
    k_cost<<<NBATCH * 32 * 32, 256>>>(x, y, C);
    k_dummy<<<1, 32>>>();   // keeps ncu capture slot on the first u half-sweep
    for (int it = 0; it < MAX_IT; it++) {
        k_sweep<<<1024, 256>>>(C, 0, it);   // u(A), batches 0-3 ascending
        k_vcol<<<256, 512>>>(C, 0, it);     // v(A), batches 3->0 descending
        k_sweep<<<1024, 256>>>(C, 4, it);   // u(B), batches 4-7 ascending
        k_vcol<<<256, 512>>>(C, 4, it);     // v(B), batches 7->4 descending
    }
    k_pi<<<NROWS / 8, 256>>>(C, pi, cost);
}

// round 15
// speedup vs baseline: 2.5209x; 2.0184x over previous
#include <cuda_runtime.h>
#include <math.h>

// Problem constants
#define NBATCH 8
#define NPTS   2048
#define NFEAT  32
#define NROWS  (NBATCH * NPTS)                       // 16384
#define NMAT   ((size_t)NBATCH * NPTS * NPTS)        // 33554432
#define MAX_IT 100

// eps = 0.1 ; log2-domain scale: (1/eps) * log2(e)
#define S2   14.4269504088896341f
#define LN2  0.6931471805599453f
#define EPSV 0.1f
#define LOG_MUV (logf(1.0f / 2048.0f + 1e-8f))      // == log_nu (N == M)
#define ERR_THRESH_SUM 0.8f

// Scratch (__device__ globals; no allocation allowed)
__device__ __align__(16) float g_u[NROWS];
__device__ __align__(16) float g_v[NROWS];
__device__ float g_err[MAX_IT];

__device__ __forceinline__ float ex2f(float x) {
    float y;
    asm("ex2.approx.ftz.f32 %0, %1;" : "=f"(y) : "f"(x));
    return y;
}
__device__ __forceinline__ float lg2f(float x) {
    float y;
    asm("lg2.approx.ftz.f32 %0, %1;" : "=f"(y) : "f"(x));
    return y;
}

// ---------------------------------------------------------------------------
// Init
// ---------------------------------------------------------------------------
__global__ void k_init(float* __restrict__ cost) {
    int t = blockIdx.x * blockDim.x + threadIdx.x;
    int n = gridDim.x * blockDim.x;
    for (int i = t; i < NROWS; i += n) {
        g_u[i] = 0.0f;
        g_v[i] = 0.0f;
    }
    if (t < MAX_IT) g_err[t] = 0.0f;
    if (t < NBATCH) cost[t] = 0.0f;
}

// Dummy no-op: keeps the ncu capture slot aligned onto the first u-sweep.
__global__ void k_dummy() {}

// ---------------------------------------------------------------------------
// Cost matrix: C[b,i,j] = sum_d (x[b,i,d] - y[b,j,d])^2
// ---------------------------------------------------------------------------
__global__ void __launch_bounds__(256) k_cost(const float* __restrict__ x,
                                              const float* __restrict__ y,
                                              float* __restrict__ C) {
    __shared__ float xs[NFEAT * 65];
    __shared__ float ys[NFEAT * 65];

    int tile = blockIdx.x;          // 8192 tiles of 64x64
    int b  = tile >> 10;
    int ti = (tile >> 5) & 31;
    int tj = tile & 31;
    int tid = threadIdx.x;

    const float* xb = x + ((size_t)b * NPTS + (size_t)ti * 64) * NFEAT;
    const float* yb = y + ((size_t)b * NPTS + (size_t)tj * 64) * NFEAT;

    for (int e = tid; e < 64 * NFEAT; e += 256) {
        int row = e >> 5;
        int d   = e & 31;
        xs[d * 65 + row] = xb[e];
        ys[d * 65 + row] = yb[e];
    }
    __syncthreads();

    int ri = (tid >> 4) << 2;
    int cj = (tid & 15) << 2;

    float acc[4][4];
#pragma unroll
    for (int a = 0; a < 4; a++)
#pragma unroll
        for (int c = 0; c < 4; c++) acc[a][c] = 0.0f;

#pragma unroll
    for (int d = 0; d < NFEAT; d++) {
        float xa[4], yv[4];
#pragma unroll
        for (int a = 0; a < 4; a++) xa[a] = xs[d * 65 + ri + a];
#pragma unroll
        for (int c = 0; c < 4; c++) yv[c] = ys[d * 65 + cj + c];
#pragma unroll
        for (int a = 0; a < 4; a++)
#pragma unroll
            for (int c = 0; c < 4; c++) {
                float diff = xa[a] - yv[c];
                acc[a][c] = fmaf(diff, diff, acc[a][c]);
            }
    }

    float* Cb = C + (size_t)b * NPTS * NPTS + (size_t)(ti * 64 + ri) * NPTS + (tj * 64 + cj);
#pragma unroll
    for (int a = 0; a < 4; a++) {
        float4 o = make_float4(acc[a][0], acc[a][1], acc[a][2], acc[a][3]);
        *reinterpret_cast<float4*>(Cb + (size_t)a * NPTS) = o;
    }
}

// ---------------------------------------------------------------------------
// u-sweep (row LSE over C, row-major). R12 shape: 2048 blocks x 256 thr,
// warp per row, dual online-LSE chains. NEW: explicit register prefetch —
// step g's loads are issued during step g-1's math (dedicated p0/p1 regs),
// structurally forcing load->use distance of one full unrolled step.
// __launch_bounds__(256, 6): allow up to ~42 regs (48 warps/SM, 75% occ).
// ---------------------------------------------------------------------------
__global__ void __launch_bounds__(256, 6) k_sweep(const float* __restrict__ M,
                                                  const float* __restrict__ oth,
                                                  float* __restrict__ mine,
                                                  int it, int track_err) {
    if (it > 0 && g_err[it - 1] < ERR_THRESH_SUM) return;

    __shared__ float oS2[NPTS];          // 8 KB : other potential * S2
    __shared__ float blkerr;

    int blk = blockIdx.x;                // 2048 blocks, 8 rows each
    int b   = blk >> 8;
    int tid = threadIdx.x;
    int w   = tid >> 5;
    int l   = tid & 31;

    const float4* og  = reinterpret_cast<const float4*>(oth + (b << 11));
    float4*       os4 = reinterpret_cast<float4*>(oS2);
#pragma unroll
    for (int k = 0; k < 2; k++) {
        float4 t = og[tid + (k << 8)];
        t.x *= S2; t.y *= S2; t.z *= S2; t.w *= S2;
        os4[tid + (k << 8)] = t;
    }
    if (tid == 0) blkerr = 0.0f;
    __syncthreads();

    int r = (blk << 3) + w;              // global row index
    const float4* Mr = reinterpret_cast<const float4*>(M + ((size_t)r << 11));

    // prefetch step 0
    float4 p0 = Mr[l];
    float4 p1 = Mr[l + 32];

    float m0 = -1e30f, s0 = 0.0f, m1 = -1e30f, s1 = 0.0f;
#pragma unroll
    for (int g = 0; g < 8; g++) {
        int idx = l + (g << 6);
        float4 c0 = p0;
        float4 c1 = p1;
        if (g < 7) {                     // issue next step's loads NOW
            p0 = Mr[idx + 64];
            p1 = Mr[idx + 96];
        }
        float4 v0 = os4[idx];
        float4 v1 = os4[idx + 32];
        float t0 = fmaf(-S2, c0.x, v0.x);
        float t1 = fmaf(-S2, c0.y, v0.y);
        float t2 = fmaf(-S2, c0.z, v0.z);
        float t3 = fmaf(-S2, c0.w, v0.w);
        float t4 = fmaf(-S2, c1.x, v1.x);
        float t5 = fmaf(-S2, c1.y, v1.y);
        float t6 = fmaf(-S2, c1.z, v1.z);
        float t7 = fmaf(-S2, c1.w, v1.w);
        float mA = fmaxf(fmaxf(t0, t1), fmaxf(t2, t3));
        float n0 = fmaxf(m0, mA);
        s0 = s0 * ex2f(m0 - n0)
           + ((ex2f(t0 - n0) + ex2f(t1 - n0)) + (ex2f(t2 - n0) + ex2f(t3 - n0)));
        m0 = n0;
        float mB = fmaxf(fmaxf(t4, t5), fmaxf(t6, t7));
        float n1 = fmaxf(m1, mB);
        s1 = s1 * ex2f(m1 - n1)
           + ((ex2f(t4 - n1) + ex2f(t5 - n1)) + (ex2f(t6 - n1) + ex2f(t7 - n1)));
        m1 = n1;
    }
    float m = fmaxf(m0, m1);
    float s = s0 * ex2f(m0 - m) + s1 * ex2f(m1 - m);
#pragma unroll
    for (int o = 16; o; o >>= 1) {
        float mo = __shfl_xor_sync(0xffffffffu, m, o);
        float so = __shfl_xor_sync(0xffffffffu, s, o);
        float nm = fmaxf(m, mo);
        s = s * ex2f(m - nm) + so * ex2f(mo - nm);
        m = nm;
    }
    if (l == 0) {
        float lse  = (m + lg2f(s)) * LN2;
        float pnew = EPSV * (LOG_MUV - lse);
        if (track_err) {
            float du = fabsf(pnew - mine[r]);
            atomicAdd(&blkerr, du);
        }
        mine[r] = pnew;
    }
    if (track_err) {
        __syncthreads();
        if (tid == 0) atomicAdd(&g_err[it], blkerr);
    }
}

// ---------------------------------------------------------------------------
// v-sweep: column LSE over C itself (no transposed copy).  [R12, unchanged]
//   v_j = eps * (log_nu - lse_i((u_i - C_ij)/eps))
// Block = 512 threads (16 warps), 32 columns; warp w owns rows [w*128, +128).
// 512 blocks = one wave; batches DESCENDING so the sweep ends on b0, which
// the next u-sweep (ascending) reads first -> circular L2 reuse of C.
// ---------------------------------------------------------------------------
__global__ void __launch_bounds__(512) k_vcol(const float* __restrict__ C, int it) {
    if (it > 0 && g_err[it - 1] < ERR_THRESH_SUM) return;

    __shared__ float uS2_s[NPTS];        // 8 KB : u * S2
    __shared__ float pm_s[16 * 32];
    __shared__ float ps_s[16 * 32];

    int blk = blockIdx.x;                // 512 blocks
    int b   = 7 - (blk >> 6);            // descending batches
    int jg  = blk & 63;                  // column group (32 cols)
    int tid = threadIdx.x;
    int w   = tid >> 5;
    int l   = tid & 31;

    const float4* ug  = reinterpret_cast<const float4*>(g_u + (b << 11));
    float4*       us4 = reinterpret_cast<float4*>(uS2_s);
    {
        float4 t = ug[tid];
        t.x *= S2; t.y *= S2; t.z *= S2; t.w *= S2;
        us4[tid] = t;
    }
    __syncthreads();

    int j = (jg << 5) + l;               // this thread's column
    const float* Cb = C + ((size_t)b << 22) + j;

    float m0 = -1e30f, s0 = 0.0f, m1 = -1e30f, s1 = 0.0f;
    int i0 = w << 7;                     // warp's 128-row segment
#pragma unroll 2
    for (int g = 0; g < 16; g++) {
        int i = i0 + (g << 3);
        const float* Ci = Cb + ((size_t)i << 11);
        float c0 = Ci[0];
        float c1 = Ci[(size_t)1 << 11];
        float c2 = Ci[(size_t)2 << 11];
        float c3 = Ci[(size_t)3 << 11];
        float c4 = Ci[(size_t)4 << 11];
        float c5 = Ci[(size_t)5 << 11];
        float c6 = Ci[(size_t)6 << 11];
        float c7 = Ci[(size_t)7 << 11];
        float t0 = fmaf(-S2, c0, uS2_s[i + 0]);
        float t1 = fmaf(-S2, c1, uS2_s[i + 1]);
        float t2 = fmaf(-S2, c2, uS2_s[i + 2]);
        float t3 = fmaf(-S2, c3, uS2_s[i + 3]);
        float t4 = fmaf(-S2, c4, uS2_s[i + 4]);
        float t5 = fmaf(-S2, c5, uS2_s[i + 5]);
        float t6 = fmaf(-S2, c6, uS2_s[i + 6]);
        float t7 = fmaf(-S2, c7, uS2_s[i + 7]);
        float mA = fmaxf(fmaxf(t0, t1), fmaxf(t2, t3));
        float n0 = fmaxf(m0, mA);
        s0 = s0 * ex2f(m0 - n0)
           + ((ex2f(t0 - n0) + ex2f(t1 - n0)) + (ex2f(t2 - n0) + ex2f(t3 - n0)));
        m0 = n0;
        float mB = fmaxf(fmaxf(t4, t5), fmaxf(t6, t7));
        float n1 = fmaxf(m1, mB);
        s1 = s1 * ex2f(m1 - n1)
           + ((ex2f(t4 - n1) + ex2f(t5 - n1)) + (ex2f(t6 - n1) + ex2f(t7 - n1)));
        m1 = n1;
    }
    float m = fmaxf(m0, m1);
    float s = s0 * ex2f(m0 - m) + s1 * ex2f(m1 - m);
    pm_s[(w << 5) + l] = m;
    ps_s[(w << 5) + l] = s;
    __syncthreads();

    if (w == 0) {
        float mm = pm_s[l], ss = ps_s[l];
#pragma unroll
        for (int k = 1; k < 16; k++) {
            float mo = pm_s[(k << 5) + l];
            float so = ps_s[(k << 5) + l];
            float nm = fmaxf(mm, mo);
            ss = ss * ex2f(mm - nm) + so * ex2f(mo - nm);
            mm = nm;
        }
        g_v[(b << 11) + j] = EPSV * (LOG_MUV - (mm + lg2f(ss)) * LN2);
    }
}

// ---------------------------------------------------------------------------
// Epilogue: pi = exp((u_i + v_j - C_ij)/eps), cost[b] = sum pi*C
// ---------------------------------------------------------------------------
__global__ void __launch_bounds__(256) k_pi(const float* __restrict__ C,
                                            float* __restrict__ pi,
                                            float* __restrict__ cost) {
    __shared__ float blkcost;
    if (threadIdx.x == 0) blkcost = 0.0f;
    __syncthreads();

    int warp = (blockIdx.x << 3) + (threadIdx.x >> 5);
    int lane = threadIdx.x & 31;
    int r = warp;
    int b = r >> 11;

    float u = g_u[r];
    const float4* Cr = reinterpret_cast<const float4*>(C + (size_t)r * NPTS);
    const float4* Vr = reinterpret_cast<const float4*>(g_v + (b << 11));
    float4* Pr = reinterpret_cast<float4*>(pi + (size_t)r * NPTS);

    float acc = 0.0f;
#pragma unroll 4
    for (int k = lane; k < NPTS / 4; k += 32) {
        float4 c = Cr[k];
        float4 v = Vr[k];
        float4 p;
        p.x = ex2f((u + v.x - c.x) * S2);
        p.y = ex2f((u + v.y - c.y) * S2);
        p.z = ex2f((u + v.z - c.z) * S2);
        p.w = ex2f((u + v.w - c.w) * S2);
        Pr[k] = p;
        acc += p.x * c.x + p.y * c.y + p.z * c.z + p.w * c.w;
    }
#pragma unroll
    for (int o = 16; o; o >>= 1) acc += __shfl_xor_sync(0xffffffffu, acc, o);
    if (lane == 0) atomicAdd(&blkcost, acc);
    __syncthreads();
    if (threadIdx.x == 0) atomicAdd(&cost[b], blkcost);
}

// ---------------------------------------------------------------------------
// Launch: init -> cost -> dummy -> 100 x (u-sweep rows of C, v-sweep cols of C)
// -> pi. Output layout (tuple order): cost[8] | pi | C.
// ---------------------------------------------------------------------------
extern "C" void kernel_launch(void* const* d_in, const int* in_sizes, int n_in,
                              void* d_out, int out_size) {
    const float* x = (const float*)d_in[0];
    const float* y = (const float*)d_in[1];
    float* out  = (float*)d_out;
    float* cost = out;
    float* pi   = out + NBATCH;
    float* C    = out + NBATCH + NMAT;

    float* u;
    cudaGetSymbolAddress((void**)&u, g_u);
    float* v;
    cudaGetSymbolAddress((void**)&v, g_v);

    k_init<<<64, 256>>>(cost);
    k_cost<<<NBATCH * 32 * 32, 256>>>(x, y, C);
    k_dummy<<<1, 32>>>();   // keeps ncu capture slot on the first u-sweep
    for (int it = 0; it < MAX_IT; it++) {
        k_sweep<<<NROWS / 8, 256>>>(C, v, u, it, 1);   // u update (tracks err)
        k_vcol<<<512, 512>>>(C, it);                   // v update, column LSE
    }
    k_pi<<<NROWS / 8, 256>>>(C, pi, cost);
}